// round 2
// baseline (speedup 1.0000x reference)
#include <cuda_runtime.h>
#include <cuda_bf16.h>
#include <math.h>

// ---------------- problem dims ----------------
#define S_TOK   8192
#define HDIM    1024
#define EXP     8
#define IDIM    4096
#define CAP     2048

// ---------------- scratch (device globals; no allocation allowed) ----------------
__device__ float g_ln[(size_t)S_TOK * HDIM];        // 32 MB  LN'ed tokens
__device__ float g_h[(size_t)S_TOK * IDIM];         // 128 MB GEMM1 output (compact rows)
__device__ int   g_top1[S_TOK];
__device__ float g_w[S_TOK];
__device__ int   g_perm[S_TOK];
__device__ int   g_off[EXP + 1];

// =====================================================================
// K1: LayerNorm + residual copy + gating logits/softmax/argmax
// one block per token, 256 threads, 4 floats (one float4) per thread
// =====================================================================
__global__ void __launch_bounds__(256) ln_gate_kernel(
    const float4* __restrict__ in4,
    const float4* __restrict__ gw4,     // [E, 256] float4
    const float4* __restrict__ gamma4,
    const float4* __restrict__ beta4,
    float4* __restrict__ out4)
{
    const int s   = blockIdx.x;
    const int tid = threadIdx.x;
    const int lane = tid & 31, wid = tid >> 5;

    float4 x = in4[(size_t)s * 256 + tid];

    float lsum = x.x + x.y + x.z + x.w;
    float lsq  = x.x * x.x + x.y * x.y + x.z * x.z + x.w * x.w;
    #pragma unroll
    for (int off = 16; off > 0; off >>= 1) {
        lsum += __shfl_down_sync(0xffffffffu, lsum, off);
        lsq  += __shfl_down_sync(0xffffffffu, lsq,  off);
    }
    __shared__ float s_a[8], s_b[8];
    if (lane == 0) { s_a[wid] = lsum; s_b[wid] = lsq; }
    __syncthreads();
    __shared__ float s_mean, s_rstd;
    if (tid == 0) {
        float a = 0.f, b = 0.f;
        #pragma unroll
        for (int w = 0; w < 8; w++) { a += s_a[w]; b += s_b[w]; }
        float mean = a * (1.0f / HDIM);
        float var  = b * (1.0f / HDIM) - mean * mean;
        s_mean = mean;
        s_rstd = rsqrtf(var + 1e-5f);
    }
    __syncthreads();
    const float mean = s_mean, rstd = s_rstd;

    float4 g = gamma4[tid], bb = beta4[tid];
    float4 nrm;
    nrm.x = (x.x - mean) * rstd * g.x + bb.x;
    nrm.y = (x.y - mean) * rstd * g.y + bb.y;
    nrm.z = (x.z - mean) * rstd * g.z + bb.z;
    nrm.w = (x.w - mean) * rstd * g.w + bb.w;

    reinterpret_cast<float4*>(g_ln)[(size_t)s * 256 + tid] = nrm;
    out4[(size_t)s * 256 + tid] = x;   // residual pre-fill (covers dropped tokens)

    // gating logits: 8 experts
    float p[EXP];
    #pragma unroll
    for (int e = 0; e < EXP; e++) {
        float4 w = gw4[(size_t)e * 256 + tid];
        p[e] = nrm.x * w.x + nrm.y * w.y + nrm.z * w.z + nrm.w * w.w;
    }
    #pragma unroll
    for (int e = 0; e < EXP; e++) {
        #pragma unroll
        for (int off = 16; off > 0; off >>= 1)
            p[e] += __shfl_down_sync(0xffffffffu, p[e], off);
    }
    __shared__ float s_l[EXP][8];
    if (lane == 0) {
        #pragma unroll
        for (int e = 0; e < EXP; e++) s_l[e][wid] = p[e];
    }
    __syncthreads();
    if (tid == 0) {
        float logit[EXP];
        #pragma unroll
        for (int e = 0; e < EXP; e++) {
            float v = 0.f;
            #pragma unroll
            for (int w = 0; w < 8; w++) v += s_l[e][w];
            logit[e] = v;
        }
        int best = 0; float bv = logit[0];
        #pragma unroll
        for (int e = 1; e < EXP; e++) if (logit[e] > bv) { bv = logit[e]; best = e; }
        float den = 0.f;
        #pragma unroll
        for (int e = 0; e < EXP; e++) den += expf(logit[e] - bv);
        g_top1[s] = best;
        g_w[s]    = 1.0f / den;   // exp(0)/den = prob of argmax
    }
}

// =====================================================================
// K2: exact token-order exclusive cumsum per expert, capacity drop,
// compact permutation + expert offsets. 1 block, 1024 threads, 8 tok/thread.
// =====================================================================
__global__ void __launch_bounds__(1024) scan_kernel()
{
    __shared__ int s_scan[1024];
    __shared__ int s_tot[EXP];
    __shared__ int s_koff[EXP + 1];

    const int tid = threadIdx.x;
    int t[8];
    int c[EXP];
    #pragma unroll
    for (int e = 0; e < EXP; e++) c[e] = 0;
    #pragma unroll
    for (int j = 0; j < 8; j++) {
        t[j] = g_top1[tid * 8 + j];
        c[t[j]]++;
    }
    int excl[EXP];
    for (int e = 0; e < EXP; e++) {
        s_scan[tid] = c[e];
        __syncthreads();
        for (int off = 1; off < 1024; off <<= 1) {
            int v = (tid >= off) ? s_scan[tid - off] : 0;
            __syncthreads();
            s_scan[tid] += v;
            __syncthreads();
        }
        excl[e] = s_scan[tid] - c[e];
        if (tid == 1023) s_tot[e] = s_scan[1023];
        __syncthreads();
    }
    if (tid == 0) {
        int o = 0;
        #pragma unroll
        for (int e = 0; e < EXP; e++) {
            s_koff[e] = o;
            o += min(s_tot[e], CAP);
        }
        s_koff[EXP] = o;
        #pragma unroll
        for (int i = 0; i <= EXP; i++) g_off[i] = s_koff[i];
    }
    __syncthreads();
    #pragma unroll
    for (int j = 0; j < 8; j++) {
        int e = t[j];
        int r = excl[e]++;
        int s = tid * 8 + j;
        if (r < CAP) g_perm[s_koff[e] + r] = s;
        else         g_w[s] = 0.0f;          // dropped token -> zero weight
    }
}

// =====================================================================
// GEMM1: H1[r, n] = gelu( sum_k ln[perm[r], k] * wi[e, k, n] )
// BM=128, BN=128, BK=16, 256 threads, 8x8 micro-tile. K = HDIM = 1024.
// =====================================================================
#define BM 128
#define BN 128
#define BK 16

__global__ void __launch_bounds__(256) gemm1_kernel(const float* __restrict__ wi)
{
    const int e = blockIdx.z;
    const int row0 = g_off[e];
    const int ne   = g_off[e + 1] - row0;
    const int m0   = blockIdx.y * BM;
    if (m0 >= ne) return;
    const int mrows = min(BM, ne - m0);
    const int n0 = blockIdx.x * BN;

    __shared__ float As[BK][BM + 4];
    __shared__ float Bs[BK][BN];
    __shared__ int   sp[BM];

    const int tid = threadIdx.x;
    if (tid < BM) sp[tid] = (tid < mrows) ? g_perm[row0 + m0 + tid] : 0;
    __syncthreads();

    const float* Bp = wi + (size_t)e * HDIM * IDIM + n0;

    float acc[8][8];
    #pragma unroll
    for (int i = 0; i < 8; i++)
        #pragma unroll
        for (int j = 0; j < 8; j++) acc[i][j] = 0.f;

    const int tx = tid & 15, ty = tid >> 4;
    const int a_lk = tid & 3, a_lm = tid >> 2;   // A: 4 k-groups x 64 rows
    const int b_ln = tid & 31, b_lk = tid >> 5;  // B: 32 n-groups x 8 k

    for (int k0 = 0; k0 < HDIM; k0 += BK) {
        #pragma unroll
        for (int rr = 0; rr < 2; rr++) {
            int r = a_lm + rr * 64;
            float4 v = make_float4(0.f, 0.f, 0.f, 0.f);
            if (r < mrows)
                v = *reinterpret_cast<const float4*>(&g_ln[(size_t)sp[r] * HDIM + k0 + a_lk * 4]);
            As[a_lk * 4 + 0][r] = v.x;
            As[a_lk * 4 + 1][r] = v.y;
            As[a_lk * 4 + 2][r] = v.z;
            As[a_lk * 4 + 3][r] = v.w;
        }
        #pragma unroll
        for (int kk = 0; kk < 2; kk++) {
            int k = b_lk + kk * 8;
            float4 v = *reinterpret_cast<const float4*>(&Bp[(size_t)(k0 + k) * IDIM + b_ln * 4]);
            *reinterpret_cast<float4*>(&Bs[k][b_ln * 4]) = v;
        }
        __syncthreads();
        #pragma unroll
        for (int k = 0; k < BK; k++) {
            float ra[8], rb[8];
            #pragma unroll
            for (int i = 0; i < 8; i++) ra[i] = As[k][ty * 8 + i];
            #pragma unroll
            for (int j = 0; j < 8; j++) rb[j] = Bs[k][tx * 8 + j];
            #pragma unroll
            for (int i = 0; i < 8; i++)
                #pragma unroll
                for (int j = 0; j < 8; j++) acc[i][j] += ra[i] * rb[j];
        }
        __syncthreads();
    }

    // epilogue: exact GELU, vectorized store to compact h buffer
    #pragma unroll
    for (int i = 0; i < 8; i++) {
        int m = ty * 8 + i;
        if (m < mrows) {
            float tmp[8];
            #pragma unroll
            for (int j = 0; j < 8; j++) {
                float x = acc[i][j];
                tmp[j] = 0.5f * x * (1.0f + erff(x * 0.70710678118654752f));
            }
            size_t base = (size_t)(row0 + m0 + m) * IDIM + n0 + tx * 8;
            *reinterpret_cast<float4*>(&g_h[base])     = make_float4(tmp[0], tmp[1], tmp[2], tmp[3]);
            *reinterpret_cast<float4*>(&g_h[base + 4]) = make_float4(tmp[4], tmp[5], tmp[6], tmp[7]);
        }
    }
}

// =====================================================================
// GEMM2: out[tok, n] = inputs[tok, n] + w[tok] * sum_k h[r, k] * wo[e, k, n]
// K = IDIM = 4096, N = HDIM = 1024.
// =====================================================================
__global__ void __launch_bounds__(256) gemm2_kernel(
    const float* __restrict__ wo,
    const float* __restrict__ inp,
    float* __restrict__ out)
{
    const int e = blockIdx.z;
    const int row0 = g_off[e];
    const int ne   = g_off[e + 1] - row0;
    const int m0   = blockIdx.y * BM;
    if (m0 >= ne) return;
    const int mrows = min(BM, ne - m0);
    const int n0 = blockIdx.x * BN;

    __shared__ float As[BK][BM + 4];
    __shared__ float Bs[BK][BN];
    __shared__ int   sp[BM];

    const int tid = threadIdx.x;
    if (tid < BM) sp[tid] = (tid < mrows) ? g_perm[row0 + m0 + tid] : 0;
    __syncthreads();

    const float* Bp = wo + (size_t)e * IDIM * HDIM + n0;

    float acc[8][8];
    #pragma unroll
    for (int i = 0; i < 8; i++)
        #pragma unroll
        for (int j = 0; j < 8; j++) acc[i][j] = 0.f;

    const int tx = tid & 15, ty = tid >> 4;
    const int a_lk = tid & 3, a_lm = tid >> 2;
    const int b_ln = tid & 31, b_lk = tid >> 5;

    for (int k0 = 0; k0 < IDIM; k0 += BK) {
        #pragma unroll
        for (int rr = 0; rr < 2; rr++) {
            int r = a_lm + rr * 64;
            float4 v = make_float4(0.f, 0.f, 0.f, 0.f);
            if (r < mrows)
                v = *reinterpret_cast<const float4*>(&g_h[(size_t)(row0 + m0 + r) * IDIM + k0 + a_lk * 4]);
            As[a_lk * 4 + 0][r] = v.x;
            As[a_lk * 4 + 1][r] = v.y;
            As[a_lk * 4 + 2][r] = v.z;
            As[a_lk * 4 + 3][r] = v.w;
        }
        #pragma unroll
        for (int kk = 0; kk < 2; kk++) {
            int k = b_lk + kk * 8;
            float4 v = *reinterpret_cast<const float4*>(&Bp[(size_t)(k0 + k) * HDIM + b_ln * 4]);
            *reinterpret_cast<float4*>(&Bs[k][b_ln * 4]) = v;
        }
        __syncthreads();
        #pragma unroll
        for (int k = 0; k < BK; k++) {
            float ra[8], rb[8];
            #pragma unroll
            for (int i = 0; i < 8; i++) ra[i] = As[k][ty * 8 + i];
            #pragma unroll
            for (int j = 0; j < 8; j++) rb[j] = Bs[k][tx * 8 + j];
            #pragma unroll
            for (int i = 0; i < 8; i++)
                #pragma unroll
                for (int j = 0; j < 8; j++) acc[i][j] += ra[i] * rb[j];
        }
        __syncthreads();
    }

    // epilogue: combine with residual, scatter to token rows
    #pragma unroll
    for (int i = 0; i < 8; i++) {
        int m = ty * 8 + i;
        if (m < mrows) {
            int tok = sp[m];
            float w = g_w[tok];
            size_t base = (size_t)tok * HDIM + n0 + tx * 8;
            float4 r0v = *reinterpret_cast<const float4*>(&inp[base]);
            float4 r1v = *reinterpret_cast<const float4*>(&inp[base + 4]);
            float4 o0, o1;
            o0.x = r0v.x + w * acc[i][0];
            o0.y = r0v.y + w * acc[i][1];
            o0.z = r0v.z + w * acc[i][2];
            o0.w = r0v.w + w * acc[i][3];
            o1.x = r1v.x + w * acc[i][4];
            o1.y = r1v.y + w * acc[i][5];
            o1.z = r1v.z + w * acc[i][6];
            o1.w = r1v.w + w * acc[i][7];
            *reinterpret_cast<float4*>(&out[base])     = o0;
            *reinterpret_cast<float4*>(&out[base + 4]) = o1;
        }
    }
}

// =====================================================================
extern "C" void kernel_launch(void* const* d_in, const int* in_sizes, int n_in,
                              void* d_out, int out_size)
{
    const float* inputs = (const float*)d_in[0];   // [4,2048,1024]
    const float* gw     = (const float*)d_in[1];   // [8,1024]
    const float* gamma  = (const float*)d_in[2];   // [1024]
    const float* beta   = (const float*)d_in[3];   // [1024]
    const float* wi     = (const float*)d_in[4];   // [8,1024,4096]
    const float* wo     = (const float*)d_in[5];   // [8,4096,1024]
    // d_in[6..11] = LayerSkip heads: outputs unused -> skipped
    float* out = (float*)d_out;

    ln_gate_kernel<<<S_TOK, 256>>>(
        (const float4*)inputs, (const float4*)gw,
        (const float4*)gamma, (const float4*)beta, (float4*)out);

    scan_kernel<<<1, 1024>>>();

    gemm1_kernel<<<dim3(IDIM / BN, CAP / BM, EXP), 256>>>(wi);

    gemm2_kernel<<<dim3(HDIM / BN, CAP / BM, EXP), 256>>>(wo, inputs, out);
}

// round 5
// speedup vs baseline: 4.8051x; 4.8051x over previous
#include <cuda_runtime.h>
#include <cuda_bf16.h>
#include <math.h>
#include <stdint.h>
#include <cstdint>

// ---------------- problem dims ----------------
#define S_TOK   8192
#define HDIM    1024
#define EXP     8
#define IDIM    4096
#define CAP     2048

// ---------------- scratch (device globals) ----------------
__device__ __nv_bfloat16 g_lnb[(size_t)S_TOK * HDIM];        // 16 MB LN'ed tokens (bf16)
__device__ __nv_bfloat16 g_hb [(size_t)S_TOK * IDIM];        // 64 MB GEMM1 output (bf16, compact rows)
__device__ __nv_bfloat16 g_wib[(size_t)EXP * IDIM * HDIM];   // 64 MB wi transposed: [e][n=IDIM][k=HDIM]
__device__ __nv_bfloat16 g_wob[(size_t)EXP * HDIM * IDIM];   // 64 MB wo transposed: [e][n=HDIM][k=IDIM]
__device__ int   g_top1[S_TOK];
__device__ float g_w[S_TOK];
__device__ int   g_perm[S_TOK];
__device__ int   g_off[EXP + 1];

__device__ __forceinline__ uint32_t smem_u32(const void* p) {
    return (uint32_t)__cvta_generic_to_shared(p);
}

// =====================================================================
// Weight convert + transpose: src fp32 [E][R][C] -> dst bf16 [E][C][R]
// =====================================================================
template<bool WI>
__global__ void __launch_bounds__(256) transpose_conv(const float* __restrict__ src)
{
    constexpr int R = WI ? HDIM : IDIM;
    constexpr int C = WI ? IDIM : HDIM;
    __nv_bfloat16* dst = WI ? g_wib : g_wob;

    __shared__ float tile[32][33];
    const int e  = blockIdx.z;
    const int c0 = blockIdx.x * 32, r0 = blockIdx.y * 32;
    const float* s = src + (size_t)e * R * C;
    __nv_bfloat16* d = dst + (size_t)e * C * R;
    const int tx = threadIdx.x, ty = threadIdx.y;   // (32, 8)

    #pragma unroll
    for (int i = 0; i < 4; i++)
        tile[ty + i * 8][tx] = s[(size_t)(r0 + ty + i * 8) * C + c0 + tx];
    __syncthreads();
    #pragma unroll
    for (int i = 0; i < 4; i++)
        d[(size_t)(c0 + ty + i * 8) * R + r0 + tx] = __float2bfloat16(tile[tx][ty + i * 8]);
}

// =====================================================================
// K1: LayerNorm + residual copy + gating (fp32 exact) ; LN stored bf16
// =====================================================================
__global__ void __launch_bounds__(256) ln_gate_kernel(
    const float4* __restrict__ in4,
    const float4* __restrict__ gw4,
    const float4* __restrict__ gamma4,
    const float4* __restrict__ beta4,
    float4* __restrict__ out4)
{
    const int s   = blockIdx.x;
    const int tid = threadIdx.x;
    const int lane = tid & 31, wid = tid >> 5;

    float4 x = in4[(size_t)s * 256 + tid];

    float lsum = x.x + x.y + x.z + x.w;
    float lsq  = x.x * x.x + x.y * x.y + x.z * x.z + x.w * x.w;
    #pragma unroll
    for (int off = 16; off > 0; off >>= 1) {
        lsum += __shfl_down_sync(0xffffffffu, lsum, off);
        lsq  += __shfl_down_sync(0xffffffffu, lsq,  off);
    }
    __shared__ float s_a[8], s_b[8];
    if (lane == 0) { s_a[wid] = lsum; s_b[wid] = lsq; }
    __syncthreads();
    __shared__ float s_mean, s_rstd;
    if (tid == 0) {
        float a = 0.f, b = 0.f;
        #pragma unroll
        for (int w = 0; w < 8; w++) { a += s_a[w]; b += s_b[w]; }
        float mean = a * (1.0f / HDIM);
        float var  = b * (1.0f / HDIM) - mean * mean;
        s_mean = mean;
        s_rstd = rsqrtf(var + 1e-5f);
    }
    __syncthreads();
    const float mean = s_mean, rstd = s_rstd;

    float4 g = gamma4[tid], bb = beta4[tid];
    float4 nrm;
    nrm.x = (x.x - mean) * rstd * g.x + bb.x;
    nrm.y = (x.y - mean) * rstd * g.y + bb.y;
    nrm.z = (x.z - mean) * rstd * g.z + bb.z;
    nrm.w = (x.w - mean) * rstd * g.w + bb.w;

    // store LN tokens as bf16 (GEMM1 A operand)
    __nv_bfloat162 p0 = __floats2bfloat162_rn(nrm.x, nrm.y);
    __nv_bfloat162 p1 = __floats2bfloat162_rn(nrm.z, nrm.w);
    uint32_t* lnb32 = reinterpret_cast<uint32_t*>(g_lnb);
    lnb32[(size_t)s * 512 + tid * 2 + 0] = *reinterpret_cast<uint32_t*>(&p0);
    lnb32[(size_t)s * 512 + tid * 2 + 1] = *reinterpret_cast<uint32_t*>(&p1);

    out4[(size_t)s * 256 + tid] = x;   // residual pre-fill (covers dropped tokens)

    // gating logits (exact fp32)
    float p[EXP];
    #pragma unroll
    for (int e = 0; e < EXP; e++) {
        float4 w = gw4[(size_t)e * 256 + tid];
        p[e] = nrm.x * w.x + nrm.y * w.y + nrm.z * w.z + nrm.w * w.w;
    }
    #pragma unroll
    for (int e = 0; e < EXP; e++) {
        #pragma unroll
        for (int off = 16; off > 0; off >>= 1)
            p[e] += __shfl_down_sync(0xffffffffu, p[e], off);
    }
    __shared__ float s_l[EXP][8];
    if (lane == 0) {
        #pragma unroll
        for (int e = 0; e < EXP; e++) s_l[e][wid] = p[e];
    }
    __syncthreads();
    if (tid == 0) {
        float logit[EXP];
        #pragma unroll
        for (int e = 0; e < EXP; e++) {
            float v = 0.f;
            #pragma unroll
            for (int w = 0; w < 8; w++) v += s_l[e][w];
            logit[e] = v;
        }
        int best = 0; float bv = logit[0];
        #pragma unroll
        for (int e = 1; e < EXP; e++) if (logit[e] > bv) { bv = logit[e]; best = e; }
        float den = 0.f;
        #pragma unroll
        for (int e = 0; e < EXP; e++) den += expf(logit[e] - bv);
        g_top1[s] = best;
        g_w[s]    = 1.0f / den;
    }
}

// =====================================================================
// K2: exact token-order exclusive cumsum per expert + capacity drop
// =====================================================================
__global__ void __launch_bounds__(1024) scan_kernel()
{
    __shared__ int s_scan[1024];
    __shared__ int s_tot[EXP];
    __shared__ int s_koff[EXP + 1];

    const int tid = threadIdx.x;
    int t[8];
    int c[EXP];
    #pragma unroll
    for (int e = 0; e < EXP; e++) c[e] = 0;
    #pragma unroll
    for (int j = 0; j < 8; j++) {
        t[j] = g_top1[tid * 8 + j];
        c[t[j]]++;
    }
    int excl[EXP];
    for (int e = 0; e < EXP; e++) {
        s_scan[tid] = c[e];
        __syncthreads();
        for (int off = 1; off < 1024; off <<= 1) {
            int v = (tid >= off) ? s_scan[tid - off] : 0;
            __syncthreads();
            s_scan[tid] += v;
            __syncthreads();
        }
        excl[e] = s_scan[tid] - c[e];
        if (tid == 1023) s_tot[e] = s_scan[1023];
        __syncthreads();
    }
    if (tid == 0) {
        int o = 0;
        #pragma unroll
        for (int e = 0; e < EXP; e++) {
            s_koff[e] = o;
            o += min(s_tot[e], CAP);
        }
        s_koff[EXP] = o;
        #pragma unroll
        for (int i = 0; i <= EXP; i++) g_off[i] = s_koff[i];
    }
    __syncthreads();
    #pragma unroll
    for (int j = 0; j < 8; j++) {
        int e = t[j];
        int r = excl[e]++;
        int s = tid * 8 + j;
        if (r < CAP) g_perm[s_koff[e] + r] = s;
        else         g_w[s] = 0.0f;
    }
}

// =====================================================================
// Tensor-core GEMM (mma.sync m16n8k16 bf16, fp32 accum)
// BM=128 BN=128 BK=32, 8 warps (2Mx4N, 64x32 warp tile), 2-stage cp.async
// G1: h = gelu(ln[perm] @ wi^T-layout) -> g_hb (bf16)
// G2: out = inp + w * (h @ wo^T-layout)
// =====================================================================
#define BM 128
#define BN 128
#define BK 32
#define LDK 40    // bf16 elements per smem row (BK + 8 pad)

template<bool G1>
__global__ void __launch_bounds__(256) moe_gemm(
    const float* __restrict__ inp, float* __restrict__ out)
{
    constexpr int Kdim = G1 ? HDIM : IDIM;

    const int e    = blockIdx.z;
    const int row0 = g_off[e];
    const int ne   = g_off[e + 1] - row0;
    const int m0   = blockIdx.y * BM;
    if (m0 >= ne) return;
    const int mrows = min(BM, ne - m0);
    const int n0 = blockIdx.x * BN;

    __shared__ __nv_bfloat16 As[2][BM * LDK];
    __shared__ __nv_bfloat16 Bs[2][BN * LDK];
    __shared__ int sRow[BM];

    const int tid = threadIdx.x;
    if (tid < BM) {
        int r = min(tid, mrows - 1);
        sRow[tid] = G1 ? g_perm[row0 + m0 + r] : (row0 + m0 + r);
    }
    __syncthreads();

    const __nv_bfloat16* Abase = G1 ? g_lnb : g_hb;
    const __nv_bfloat16* Bbase = (G1 ? g_wib : g_wob)
                               + (size_t)e * (size_t)IDIM * HDIM
                               + (size_t)n0 * Kdim;

    const int warp = tid >> 5, lane = tid & 31;
    const int wm = (warp >> 2) * 64;
    const int wn = (warp & 3) * 32;

    float acc[4][4][4] = {};

    // loader: 1024 x 16B chunks per stage (A:512, B:512); each thread 4
    const int lr = tid >> 2;        // row 0..63
    const int lkg = tid & 3;        // 16B group within 32-k row

    auto load_stage = [&](int kt, int buf) {
        const int k0 = kt * BK;
        #pragma unroll
        for (int h = 0; h < 2; h++) {
            int r = lr + h * 64;
            const __nv_bfloat16* src = Abase + (size_t)sRow[r] * Kdim + k0 + lkg * 8;
            uint32_t dst = smem_u32(&As[buf][r * LDK + lkg * 8]);
            asm volatile("cp.async.cg.shared.global [%0], [%1], 16;\n" :: "r"(dst), "l"(src));
        }
        #pragma unroll
        for (int h = 0; h < 2; h++) {
            int r = lr + h * 64;
            const __nv_bfloat16* src = Bbase + (size_t)r * Kdim + k0 + lkg * 8;
            uint32_t dst = smem_u32(&Bs[buf][r * LDK + lkg * 8]);
            asm volatile("cp.async.cg.shared.global [%0], [%1], 16;\n" :: "r"(dst), "l"(src));
        }
    };

    const int KT = Kdim / BK;
    load_stage(0, 0);
    asm volatile("cp.async.commit_group;\n");

    for (int kt = 0; kt < KT; kt++) {
        const int buf = kt & 1;
        asm volatile("cp.async.wait_group 0;\n");
        __syncthreads();
        if (kt + 1 < KT) {
            load_stage(kt + 1, buf ^ 1);
            asm volatile("cp.async.commit_group;\n");
        }

        #pragma unroll
        for (int ks = 0; ks < BK; ks += 16) {
            uint32_t a[4][4];
            #pragma unroll
            for (int mi = 0; mi < 4; mi++) {
                const int amat = lane >> 3;
                const int arow = wm + mi * 16 + (lane & 7) + (amat & 1) * 8;
                const int acol = ks + (amat >> 1) * 8;
                uint32_t addr = smem_u32(&As[buf][arow * LDK + acol]);
                asm volatile("ldmatrix.sync.aligned.m8n8.x4.shared.b16 {%0,%1,%2,%3}, [%4];\n"
                    : "=r"(a[mi][0]), "=r"(a[mi][1]), "=r"(a[mi][2]), "=r"(a[mi][3]) : "r"(addr));
            }
            uint32_t b[4][2];
            #pragma unroll
            for (int p = 0; p < 2; p++) {
                const int brow = wn + p * 16 + ((lane >> 4) << 3) + (lane & 7);
                const int bcol = ks + (((lane >> 3) & 1) << 3);
                uint32_t addr = smem_u32(&Bs[buf][brow * LDK + bcol]);
                asm volatile("ldmatrix.sync.aligned.m8n8.x4.shared.b16 {%0,%1,%2,%3}, [%4];\n"
                    : "=r"(b[2*p][0]), "=r"(b[2*p][1]), "=r"(b[2*p+1][0]), "=r"(b[2*p+1][1]) : "r"(addr));
            }
            #pragma unroll
            for (int mi = 0; mi < 4; mi++)
                #pragma unroll
                for (int ni = 0; ni < 4; ni++)
                    asm volatile("mma.sync.aligned.m16n8k16.row.col.f32.bf16.bf16.f32 "
                        "{%0,%1,%2,%3},{%4,%5,%6,%7},{%8,%9},{%0,%1,%2,%3};\n"
                        : "+f"(acc[mi][ni][0]), "+f"(acc[mi][ni][1]),
                          "+f"(acc[mi][ni][2]), "+f"(acc[mi][ni][3])
                        : "r"(a[mi][0]), "r"(a[mi][1]), "r"(a[mi][2]), "r"(a[mi][3]),
                          "r"(b[ni][0]), "r"(b[ni][1]));
        }
        __syncthreads();
    }

    // ---------------- epilogue ----------------
    const int tg = lane & 3;           // col pair offset
    const int gr = lane >> 2;          // row within 8
    if (G1) {
        #pragma unroll
        for (int mi = 0; mi < 4; mi++) {
            #pragma unroll
            for (int half = 0; half < 2; half++) {
                const int m = wm + mi * 16 + gr + half * 8;
                if (m < mrows) {
                    const size_t base = (size_t)(row0 + m0 + m) * IDIM + n0 + wn;
                    #pragma unroll
                    for (int ni = 0; ni < 4; ni++) {
                        float x0 = acc[mi][ni][half * 2 + 0];
                        float x1 = acc[mi][ni][half * 2 + 1];
                        float v0 = 0.5f * x0 * (1.0f + erff(x0 * 0.70710678118654752f));
                        float v1 = 0.5f * x1 * (1.0f + erff(x1 * 0.70710678118654752f));
                        __nv_bfloat162 pk = __floats2bfloat162_rn(v0, v1);
                        *reinterpret_cast<__nv_bfloat162*>(&g_hb[base + ni * 8 + tg * 2]) = pk;
                    }
                }
            }
        }
    } else {
        #pragma unroll
        for (int mi = 0; mi < 4; mi++) {
            #pragma unroll
            for (int half = 0; half < 2; half++) {
                const int m = wm + mi * 16 + gr + half * 8;
                if (m < mrows) {
                    const int tok = g_perm[row0 + m0 + m];
                    const float w = g_w[tok];
                    const size_t base = (size_t)tok * HDIM + n0 + wn;
                    #pragma unroll
                    for (int ni = 0; ni < 4; ni++) {
                        const int col = ni * 8 + tg * 2;
                        float2 r = *reinterpret_cast<const float2*>(&inp[base + col]);
                        float2 o;
                        o.x = r.x + w * acc[mi][ni][half * 2 + 0];
                        o.y = r.y + w * acc[mi][ni][half * 2 + 1];
                        *reinterpret_cast<float2*>(&out[base + col]) = o;
                    }
                }
            }
        }
    }
}

// =====================================================================
extern "C" void kernel_launch(void* const* d_in, const int* in_sizes, int n_in,
                              void* d_out, int out_size)
{
    const float* inputs = (const float*)d_in[0];   // [4,2048,1024]
    const float* gw     = (const float*)d_in[1];   // [8,1024]
    const float* gamma  = (const float*)d_in[2];   // [1024]
    const float* beta   = (const float*)d_in[3];   // [1024]
    const float* wi     = (const float*)d_in[4];   // [8,1024,4096]
    const float* wo     = (const float*)d_in[5];   // [8,4096,1024]
    float* out = (float*)d_out;

    dim3 tb(32, 8);
    transpose_conv<true ><<<dim3(IDIM / 32, HDIM / 32, EXP), tb>>>(wi);
    transpose_conv<false><<<dim3(HDIM / 32, IDIM / 32, EXP), tb>>>(wo);

    ln_gate_kernel<<<S_TOK, 256>>>(
        (const float4*)inputs, (const float4*)gw,
        (const float4*)gamma, (const float4*)beta, (float4*)out);

    scan_kernel<<<1, 1024>>>();

    moe_gemm<true ><<<dim3(IDIM / BN, CAP / BM, EXP), 256>>>(inputs, out);
    moe_gemm<false><<<dim3(HDIM / BN, CAP / BM, EXP), 256>>>(inputs, out);
}

// round 9
// speedup vs baseline: 4.8738x; 1.0143x over previous
#include <cuda_runtime.h>
#include <cuda_bf16.h>
#include <math.h>
#include <stdint.h>

// ---------------- problem dims ----------------
#define S_TOK   8192
#define HDIM    1024
#define EXP     8
#define IDIM    4096
#define CAP     2048

// ---------------- scratch (device globals) ----------------
__device__ __nv_bfloat16 g_lnb[(size_t)S_TOK * HDIM];        // 16 MB LN'ed tokens (bf16)
__device__ __nv_bfloat16 g_hb [(size_t)S_TOK * IDIM];        // 64 MB GEMM1 output (bf16, compact rows)
__device__ __nv_bfloat16 g_wib[(size_t)EXP * IDIM * HDIM];   // 64 MB wi transposed: [e][n=IDIM][k=HDIM]
__device__ __nv_bfloat16 g_wob[(size_t)EXP * HDIM * IDIM];   // 64 MB wo transposed: [e][n=HDIM][k=IDIM]
__device__ int   g_top1[S_TOK];
__device__ float g_w[S_TOK];
__device__ int   g_perm[S_TOK];
__device__ int   g_off[EXP + 1];

__device__ __forceinline__ uint32_t smem_u32(const void* p) {
    return (uint32_t)__cvta_generic_to_shared(p);
}

// =====================================================================
// Weight convert + transpose: src fp32 [E][R][C] -> dst bf16 [E][C][R]
// (proven-correct Round-4 version)
// =====================================================================
template<bool WI>
__global__ void __launch_bounds__(256) transpose_conv(const float* __restrict__ src)
{
    constexpr int R = WI ? HDIM : IDIM;
    constexpr int C = WI ? IDIM : HDIM;
    __nv_bfloat16* dst = WI ? g_wib : g_wob;

    __shared__ float tile[32][33];
    const int e  = blockIdx.z;
    const int c0 = blockIdx.x * 32, r0 = blockIdx.y * 32;
    const float* s = src + (size_t)e * R * C;
    __nv_bfloat16* d = dst + (size_t)e * C * R;
    const int tx = threadIdx.x, ty = threadIdx.y;   // (32, 8)

    #pragma unroll
    for (int i = 0; i < 4; i++)
        tile[ty + i * 8][tx] = s[(size_t)(r0 + ty + i * 8) * C + c0 + tx];
    __syncthreads();
    #pragma unroll
    for (int i = 0; i < 4; i++)
        d[(size_t)(c0 + ty + i * 8) * R + r0 + tx] = __float2bfloat16(tile[tx][ty + i * 8]);
}

// =====================================================================
// K1: LayerNorm + residual copy + gating (fp32 exact) ; LN stored bf16
// =====================================================================
__global__ void __launch_bounds__(256) ln_gate_kernel(
    const float4* __restrict__ in4,
    const float4* __restrict__ gw4,
    const float4* __restrict__ gamma4,
    const float4* __restrict__ beta4,
    float4* __restrict__ out4)
{
    const int s   = blockIdx.x;
    const int tid = threadIdx.x;
    const int lane = tid & 31, wid = tid >> 5;

    float4 x = in4[(size_t)s * 256 + tid];

    float lsum = x.x + x.y + x.z + x.w;
    float lsq  = x.x * x.x + x.y * x.y + x.z * x.z + x.w * x.w;
    #pragma unroll
    for (int off = 16; off > 0; off >>= 1) {
        lsum += __shfl_down_sync(0xffffffffu, lsum, off);
        lsq  += __shfl_down_sync(0xffffffffu, lsq,  off);
    }
    __shared__ float s_a[8], s_b[8];
    if (lane == 0) { s_a[wid] = lsum; s_b[wid] = lsq; }
    __syncthreads();
    __shared__ float s_mean, s_rstd;
    if (tid == 0) {
        float a = 0.f, b = 0.f;
        #pragma unroll
        for (int w = 0; w < 8; w++) { a += s_a[w]; b += s_b[w]; }
        float mean = a * (1.0f / HDIM);
        float var  = b * (1.0f / HDIM) - mean * mean;
        s_mean = mean;
        s_rstd = rsqrtf(var + 1e-5f);
    }
    __syncthreads();
    const float mean = s_mean, rstd = s_rstd;

    float4 g = gamma4[tid], bb = beta4[tid];
    float4 nrm;
    nrm.x = (x.x - mean) * rstd * g.x + bb.x;
    nrm.y = (x.y - mean) * rstd * g.y + bb.y;
    nrm.z = (x.z - mean) * rstd * g.z + bb.z;
    nrm.w = (x.w - mean) * rstd * g.w + bb.w;

    __nv_bfloat162 p0 = __floats2bfloat162_rn(nrm.x, nrm.y);
    __nv_bfloat162 p1 = __floats2bfloat162_rn(nrm.z, nrm.w);
    uint32_t* lnb32 = reinterpret_cast<uint32_t*>(g_lnb);
    lnb32[(size_t)s * 512 + tid * 2 + 0] = *reinterpret_cast<uint32_t*>(&p0);
    lnb32[(size_t)s * 512 + tid * 2 + 1] = *reinterpret_cast<uint32_t*>(&p1);

    out4[(size_t)s * 256 + tid] = x;   // residual pre-fill (covers dropped tokens)

    float p[EXP];
    #pragma unroll
    for (int e = 0; e < EXP; e++) {
        float4 w = gw4[(size_t)e * 256 + tid];
        p[e] = nrm.x * w.x + nrm.y * w.y + nrm.z * w.z + nrm.w * w.w;
    }
    #pragma unroll
    for (int e = 0; e < EXP; e++) {
        #pragma unroll
        for (int off = 16; off > 0; off >>= 1)
            p[e] += __shfl_down_sync(0xffffffffu, p[e], off);
    }
    __shared__ float s_l[EXP][8];
    if (lane == 0) {
        #pragma unroll
        for (int e = 0; e < EXP; e++) s_l[e][wid] = p[e];
    }
    __syncthreads();
    if (tid == 0) {
        float logit[EXP];
        #pragma unroll
        for (int e = 0; e < EXP; e++) {
            float v = 0.f;
            #pragma unroll
            for (int w = 0; w < 8; w++) v += s_l[e][w];
            logit[e] = v;
        }
        int best = 0; float bv = logit[0];
        #pragma unroll
        for (int e = 1; e < EXP; e++) if (logit[e] > bv) { bv = logit[e]; best = e; }
        float den = 0.f;
        #pragma unroll
        for (int e = 0; e < EXP; e++) den += expf(logit[e] - bv);
        g_top1[s] = best;
        g_w[s]    = 1.0f / den;
    }
}

// =====================================================================
// K2: exact token-order exclusive cumsum per expert + capacity drop.
// Packed counts: 8 experts x 16-bit fields in a uint4 (2 per word).
// =====================================================================
__device__ __forceinline__ uint4 u4add(uint4 a, uint4 b) {
    return make_uint4(a.x + b.x, a.y + b.y, a.z + b.z, a.w + b.w);
}

__global__ void __launch_bounds__(1024) scan_kernel()
{
    __shared__ uint4 s_wt[32];
    __shared__ int   s_koff[EXP + 1];

    const int tid = threadIdx.x;
    const int lane = tid & 31, wid = tid >> 5;

    int t[8];
    uint4 cnt = make_uint4(0, 0, 0, 0);
    uint32_t* cw = reinterpret_cast<uint32_t*>(&cnt);
    #pragma unroll
    for (int j = 0; j < 8; j++) {
        t[j] = g_top1[tid * 8 + j];
        cw[t[j] >> 1] += 1u << ((t[j] & 1) * 16);
    }

    uint4 incl = cnt;
    uint32_t* iw = reinterpret_cast<uint32_t*>(&incl);
    #pragma unroll
    for (int off = 1; off < 32; off <<= 1) {
        uint4 up;
        uint32_t* uw = reinterpret_cast<uint32_t*>(&up);
        #pragma unroll
        for (int c = 0; c < 4; c++) uw[c] = __shfl_up_sync(0xffffffffu, iw[c], off);
        if (lane >= off) incl = u4add(incl, up);
    }
    if (lane == 31) s_wt[wid] = incl;
    __syncthreads();

    if (wid == 0) {
        uint4 v = s_wt[lane];
        uint32_t* vw = reinterpret_cast<uint32_t*>(&v);
        #pragma unroll
        for (int off = 1; off < 32; off <<= 1) {
            uint4 up;
            uint32_t* uw = reinterpret_cast<uint32_t*>(&up);
            #pragma unroll
            for (int c = 0; c < 4; c++) uw[c] = __shfl_up_sync(0xffffffffu, vw[c], off);
            if (lane >= off) v = u4add(v, up);
        }
        s_wt[lane] = v;
        if (lane == 31) {
            int o = 0;
            #pragma unroll
            for (int e = 0; e < EXP; e++) {
                int tot = (vw[e >> 1] >> ((e & 1) * 16)) & 0xffff;
                s_koff[e] = o;
                o += min(tot, CAP);
            }
            s_koff[EXP] = o;
            #pragma unroll
            for (int i = 0; i <= EXP; i++) g_off[i] = s_koff[i];
        }
    }
    __syncthreads();

    uint4 base = (wid > 0) ? s_wt[wid - 1] : make_uint4(0, 0, 0, 0);
    int excl[EXP];
    uint32_t* bw = reinterpret_cast<uint32_t*>(&base);
    #pragma unroll
    for (int e = 0; e < EXP; e++) {
        int sh = (e & 1) * 16;
        excl[e] = (int)(((bw[e >> 1] >> sh) & 0xffff)
                      + ((iw[e >> 1] >> sh) & 0xffff)
                      - ((cw[e >> 1] >> sh) & 0xffff));
    }
    #pragma unroll
    for (int j = 0; j < 8; j++) {
        int e = t[j];
        int r = excl[e]++;
        int s = tid * 8 + j;
        if (r < CAP) g_perm[s_koff[e] + r] = s;
        else         g_w[s] = 0.0f;
    }
}

// =====================================================================
// Tensor-core GEMM (mma.sync m16n8k16 bf16, fp32 accum)
// PROVEN Round-4 fragment path: B pre-transposed [n][k], non-trans ldmatrix.
// Upgraded to a 3-stage cp.async pipeline.
// =====================================================================
#define BM 128
#define BN 128
#define BK 32
#define LDK 40    // smem row stride (BK + 8 pad), both A and B tiles
#define STAGES 3

template<bool G1>
__global__ void __launch_bounds__(256) moe_gemm(
    const float* __restrict__ inp, float* __restrict__ out)
{
    constexpr int Kdim = G1 ? HDIM : IDIM;

    const int e    = blockIdx.z;
    const int row0 = g_off[e];
    const int ne   = g_off[e + 1] - row0;
    const int m0   = blockIdx.y * BM;
    if (m0 >= ne) return;
    const int mrows = min(BM, ne - m0);
    const int n0 = blockIdx.x * BN;

    __shared__ __nv_bfloat16 As[STAGES][BM * LDK];
    __shared__ __nv_bfloat16 Bs[STAGES][BN * LDK];
    __shared__ int sRow[BM];

    const int tid = threadIdx.x;
    if (tid < BM) {
        int r = min(tid, mrows - 1);
        sRow[tid] = G1 ? g_perm[row0 + m0 + r] : (row0 + m0 + r);
    }
    __syncthreads();

    const __nv_bfloat16* Abase = G1 ? g_lnb : g_hb;
    const __nv_bfloat16* Bbase = (G1 ? g_wib : g_wob)
                               + (size_t)e * (size_t)IDIM * HDIM
                               + (size_t)n0 * Kdim;

    const int warp = tid >> 5, lane = tid & 31;
    const int wm = (warp >> 2) * 64;
    const int wn = (warp & 3) * 32;

    float acc[4][4][4] = {};

    const int lr = tid >> 2;        // row 0..63
    const int lkg = tid & 3;        // 16B group within 32-k row

    auto load_stage = [&](int kt, int buf) {
        const int k0 = kt * BK;
        #pragma unroll
        for (int h = 0; h < 2; h++) {
            int r = lr + h * 64;
            const __nv_bfloat16* src = Abase + (size_t)sRow[r] * Kdim + k0 + lkg * 8;
            uint32_t dst = smem_u32(&As[buf][r * LDK + lkg * 8]);
            asm volatile("cp.async.cg.shared.global [%0], [%1], 16;\n" :: "r"(dst), "l"(src));
        }
        #pragma unroll
        for (int h = 0; h < 2; h++) {
            int r = lr + h * 64;
            const __nv_bfloat16* src = Bbase + (size_t)r * Kdim + k0 + lkg * 8;
            uint32_t dst = smem_u32(&Bs[buf][r * LDK + lkg * 8]);
            asm volatile("cp.async.cg.shared.global [%0], [%1], 16;\n" :: "r"(dst), "l"(src));
        }
    };

    const int KT = Kdim / BK;
    load_stage(0, 0);
    asm volatile("cp.async.commit_group;\n");
    load_stage(1, 1);
    asm volatile("cp.async.commit_group;\n");

    int buf = 0;
    for (int kt = 0; kt < KT; kt++) {
        asm volatile("cp.async.wait_group 1;\n");
        __syncthreads();
        if (kt + 2 < KT) {
            load_stage(kt + 2, (buf + 2) % STAGES);
            asm volatile("cp.async.commit_group;\n");
        } else {
            asm volatile("cp.async.commit_group;\n");   // empty: keep group count in step
        }

        #pragma unroll
        for (int ks = 0; ks < BK; ks += 16) {
            uint32_t a[4][4];
            #pragma unroll
            for (int mi = 0; mi < 4; mi++) {
                const int amat = lane >> 3;
                const int arow = wm + mi * 16 + (lane & 7) + (amat & 1) * 8;
                const int acol = ks + (amat >> 1) * 8;
                uint32_t addr = smem_u32(&As[buf][arow * LDK + acol]);
                asm volatile("ldmatrix.sync.aligned.m8n8.x4.shared.b16 {%0,%1,%2,%3}, [%4];\n"
                    : "=r"(a[mi][0]), "=r"(a[mi][1]), "=r"(a[mi][2]), "=r"(a[mi][3]) : "r"(addr));
            }
            uint32_t b[4][2];
            #pragma unroll
            for (int p = 0; p < 2; p++) {
                const int brow = wn + p * 16 + ((lane >> 4) << 3) + (lane & 7);
                const int bcol = ks + (((lane >> 3) & 1) << 3);
                uint32_t addr = smem_u32(&Bs[buf][brow * LDK + bcol]);
                asm volatile("ldmatrix.sync.aligned.m8n8.x4.shared.b16 {%0,%1,%2,%3}, [%4];\n"
                    : "=r"(b[2*p][0]), "=r"(b[2*p][1]), "=r"(b[2*p+1][0]), "=r"(b[2*p+1][1]) : "r"(addr));
            }
            #pragma unroll
            for (int mi = 0; mi < 4; mi++)
                #pragma unroll
                for (int ni = 0; ni < 4; ni++)
                    asm volatile("mma.sync.aligned.m16n8k16.row.col.f32.bf16.bf16.f32 "
                        "{%0,%1,%2,%3},{%4,%5,%6,%7},{%8,%9},{%0,%1,%2,%3};\n"
                        : "+f"(acc[mi][ni][0]), "+f"(acc[mi][ni][1]),
                          "+f"(acc[mi][ni][2]), "+f"(acc[mi][ni][3])
                        : "r"(a[mi][0]), "r"(a[mi][1]), "r"(a[mi][2]), "r"(a[mi][3]),
                          "r"(b[ni][0]), "r"(b[ni][1]));
        }
        __syncthreads();
        buf = (buf + 1) % STAGES;
    }

    // ---------------- epilogue ----------------
    const int tg = lane & 3;
    const int gr = lane >> 2;
    if (G1) {
        #pragma unroll
        for (int mi = 0; mi < 4; mi++) {
            #pragma unroll
            for (int half = 0; half < 2; half++) {
                const int m = wm + mi * 16 + gr + half * 8;
                if (m < mrows) {
                    const size_t base = (size_t)(row0 + m0 + m) * IDIM + n0 + wn;
                    #pragma unroll
                    for (int ni = 0; ni < 4; ni++) {
                        float x0 = acc[mi][ni][half * 2 + 0];
                        float x1 = acc[mi][ni][half * 2 + 1];
                        float v0 = 0.5f * x0 * (1.0f + erff(x0 * 0.70710678118654752f));
                        float v1 = 0.5f * x1 * (1.0f + erff(x1 * 0.70710678118654752f));
                        __nv_bfloat162 pk = __floats2bfloat162_rn(v0, v1);
                        *reinterpret_cast<__nv_bfloat162*>(&g_hb[base + ni * 8 + tg * 2]) = pk;
                    }
                }
            }
        }
    } else {
        #pragma unroll
        for (int mi = 0; mi < 4; mi++) {
            #pragma unroll
            for (int half = 0; half < 2; half++) {
                const int m = wm + mi * 16 + gr + half * 8;
                if (m < mrows) {
                    const int tok = g_perm[row0 + m0 + m];
                    const float w = g_w[tok];
                    const size_t base = (size_t)tok * HDIM + n0 + wn;
                    #pragma unroll
                    for (int ni = 0; ni < 4; ni++) {
                        const int col = ni * 8 + tg * 2;
                        float2 r = *reinterpret_cast<const float2*>(&inp[base + col]);
                        float2 o;
                        o.x = r.x + w * acc[mi][ni][half * 2 + 0];
                        o.y = r.y + w * acc[mi][ni][half * 2 + 1];
                        *reinterpret_cast<float2*>(&out[base + col]) = o;
                    }
                }
            }
        }
    }
}

// =====================================================================
extern "C" void kernel_launch(void* const* d_in, const int* in_sizes, int n_in,
                              void* d_out, int out_size)
{
    const float* inputs = (const float*)d_in[0];   // [4,2048,1024]
    const float* gw     = (const float*)d_in[1];   // [8,1024]
    const float* gamma  = (const float*)d_in[2];   // [1024]
    const float* beta   = (const float*)d_in[3];   // [1024]
    const float* wi     = (const float*)d_in[4];   // [8,1024,4096]
    const float* wo     = (const float*)d_in[5];   // [8,4096,1024]
    float* out = (float*)d_out;

    dim3 tb(32, 8);
    transpose_conv<true ><<<dim3(IDIM / 32, HDIM / 32, EXP), tb>>>(wi);
    transpose_conv<false><<<dim3(HDIM / 32, IDIM / 32, EXP), tb>>>(wo);

    ln_gate_kernel<<<S_TOK, 256>>>(
        (const float4*)inputs, (const float4*)gw,
        (const float4*)gamma, (const float4*)beta, (float4*)out);

    scan_kernel<<<1, 1024>>>();

    moe_gemm<true ><<<dim3(IDIM / BN, CAP / BM, EXP), 256>>>(inputs, out);
    moe_gemm<false><<<dim3(HDIM / BN, CAP / BM, EXP), 256>>>(inputs, out);
}